// round 11
// baseline (speedup 1.0000x reference)
#include <cuda_runtime.h>
#include <cuda_fp16.h>
#include <cstdint>

#define NQ    2048
#define NH    32
#define NKVH  8
#define HD    128
#define CHUNK 2048
#define TTOT  4096
#define BQ    64
#define BK    64

#define QSCALE (0.08838834764831845f * 1.4426950408889634f)

#define QPB  272
#define KPB  272
#define VPB  144

// smem layout (bytes) — 70,656 B total -> 3 CTAs/SM
#define OQ   0                 // 64 x 272
#define OK0  17408             // 64 x 272
#define OK1  34816
#define OVT  52224             // 128 x 144
#define SMB  70656

__device__ __align__(16) __half g_K [(size_t)TTOT * NKVH * HD];   // [t][kvh][hd]
__device__ __align__(16) __half g_Vt[(size_t)NKVH * HD * TTOT];   // [kvh][hd][t]

// ---------------- helpers ----------------
__device__ __forceinline__ float ex2(float x) {
    float y; asm("ex2.approx.ftz.f32 %0, %1;" : "=f"(y) : "f"(x)); return y;
}
__device__ __forceinline__ void mma16(float* d, const uint32_t* a, const uint32_t* b) {
    asm volatile(
        "mma.sync.aligned.m16n8k16.row.col.f32.f16.f16.f32 "
        "{%0,%1,%2,%3}, {%4,%5,%6,%7}, {%8,%9}, {%0,%1,%2,%3};"
        : "+f"(d[0]), "+f"(d[1]), "+f"(d[2]), "+f"(d[3])
        : "r"(a[0]), "r"(a[1]), "r"(a[2]), "r"(a[3]), "r"(b[0]), "r"(b[1]));
}
__device__ __forceinline__ void ldm4(uint32_t* r, uint32_t addr) {
    asm volatile("ldmatrix.sync.aligned.m8n8.x4.shared.b16 {%0,%1,%2,%3}, [%4];"
        : "=r"(r[0]), "=r"(r[1]), "=r"(r[2]), "=r"(r[3]) : "r"(addr));
}
__device__ __forceinline__ uint32_t s2u(const void* p) {
    uint32_t a;
    asm("{ .reg .u64 t; cvta.to.shared.u64 t, %1; cvt.u32.u64 %0, t; }" : "=r"(a) : "l"(p));
    return a;
}
__device__ __forceinline__ void cpa16(uint32_t dst, const void* src) {
    asm volatile("cp.async.cg.shared.global [%0], [%1], 16;" :: "r"(dst), "l"(src) : "memory");
}
#define CP_COMMIT() asm volatile("cp.async.commit_group;" ::: "memory")
#define CP_WAIT(n)  asm volatile("cp.async.wait_group %0;" :: "n"(n) : "memory")

// ---------------------------------------------------------------------------
// Prep kernels (unchanged)
// ---------------------------------------------------------------------------
__global__ void copy_k_kernel(const float4* __restrict__ kc) {
    int idx = blockIdx.x * blockDim.x + threadIdx.x;
    if (idx >= TTOT * NKVH * (HD / 4)) return;
    float4 a = kc[idx];
    __half2 h0 = __floats2half2_rn(a.x, a.y);
    __half2 h1 = __floats2half2_rn(a.z, a.w);
    uint2 u = {*(uint32_t*)&h0, *(uint32_t*)&h1};
    reinterpret_cast<uint2*>(g_K)[idx] = u;
}

__global__ void build_vt_kernel(const float* __restrict__ vc) {
    __shared__ float sm[32][33];
    const int t0 = blockIdx.x * 32, hd0 = blockIdx.y * 32, kvh = blockIdx.z;
    const int tx = threadIdx.x, ty = threadIdx.y;
    #pragma unroll
    for (int i = 0; i < 4; i++) {
        int t = t0 + ty + 8 * i;
        sm[ty + 8 * i][tx] = vc[((size_t)t * NKVH + kvh) * HD + hd0 + tx];
    }
    __syncthreads();
    #pragma unroll
    for (int i = 0; i < 4; i++) {
        int hd = hd0 + ty + 8 * i;
        g_Vt[((size_t)kvh * HD + hd) * TTOT + t0 + tx] = __float2half_rn(sm[tx][ty + 8 * i]);
    }
}

__global__ void scatter_kernel(const float4* __restrict__ k,
                               const float4* __restrict__ v,
                               const int* __restrict__ slot) {
    int idx = blockIdx.x * blockDim.x + threadIdx.x;
    if (idx >= NQ * NKVH * (HD / 4)) return;
    int hd4 = idx & 31, kvh = (idx >> 5) & 7, row = idx >> 8;
    int s = slot[row];
    if ((unsigned)s >= (unsigned)TTOT) return;
    float4 a = k[idx];
    __half2 h0 = __floats2half2_rn(a.x, a.y);
    __half2 h1 = __floats2half2_rn(a.z, a.w);
    uint2 u = {*(uint32_t*)&h0, *(uint32_t*)&h1};
    reinterpret_cast<uint2*>(g_K)[(s * NKVH + kvh) * 32 + hd4] = u;
    float4 b = v[idx];
    __half* vt = g_Vt + ((size_t)kvh * HD + hd4 * 4) * TTOT + s;
    vt[0]        = __float2half_rn(b.x);
    vt[TTOT]     = __float2half_rn(b.y);
    vt[2 * TTOT] = __float2half_rn(b.z);
    vt[3 * TTOT] = __float2half_rn(b.w);
}

// ---------------------------------------------------------------------------
// Attention: FA2, fp32-acc, reg-P. 1024 CTAs x 128 threads (4 warps,
// M-split 16 rows/warp, BQ=64). 70.6KB smem -> 3 independent CTAs/SM.
// K double-buffered, V single-buffered.
// ---------------------------------------------------------------------------
__global__ __launch_bounds__(128, 3)
void attn_kernel(const float* __restrict__ q, float* __restrict__ out) {
    extern __shared__ char smc[];
    const uint32_t sb = s2u(smc);

    const int tid = threadIdx.x;
    const int lane = tid & 31;
    const int w = tid >> 5;                 // 0..3
    const int g = lane >> 2, t4 = lane & 3;

    const int bid = blockIdx.x;
    const int h = bid & 31;
    const int qb = 31 - (bid >> 5);         // heavy q-blocks first
    const int kvh = h >> 2;

    const int ntiles = 33 + qb;             // (CHUNK + (qb+1)*BQ) / BK
    const int qrow0 = CHUNK + qb * BQ;

    // ldmatrix lane offsets
    const int rowA = lane & 15;
    const int colA = (lane >> 4) * 8;
    const int rowB = (lane & 7) + (lane >> 4) * 8;
    const int colB = ((lane >> 3) & 1) * 8;

    const uint32_t k0B = sb + OK0 + rowB * KPB + colB * 2;
    const uint32_t k1B = sb + OK1 + rowB * KPB + colB * 2;
    const uint32_t vB  = sb + OVT + rowB * VPB + colB * 2;

    // cp.async: K 64 rows x 256B (2 thr/row, 128B each); V 128 rows x 128B (1 thr/row)
    const int krow = tid >> 1, kch = (tid & 1) * 64;        // col in halves
    const __half* ksrc0 = g_K + ((size_t)krow * NKVH + kvh) * HD + kch;
    const uint32_t kdst0 = sb + OK0 + krow * KPB + kch * 2;
    const uint32_t kdst1 = sb + OK1 + krow * KPB + kch * 2;
    const int vrow = tid;                                    // 0..127
    const __half* vsrc0 = g_Vt + ((size_t)kvh * HD + vrow) * TTOT;
    const uint32_t vdst = sb + OVT + vrow * VPB;

    // ---- prologue: issue K(0) ----
    #pragma unroll
    for (int u = 0; u < 8; u++) cpa16(kdst0 + u * 16, ksrc0 + u * 8);
    CP_COMMIT();

    // ---- Q to smem (scaled fp16) ----
    for (int e = tid; e < BQ * (HD / 2); e += 128) {
        int r = e >> 6, c = (e & 63) * 2;
        const float* src = q + ((size_t)(qb * BQ + r) * NH + h) * HD + c;
        __half2 h2 = __floats2half2_rn(src[0] * QSCALE, src[1] * QSCALE);
        *reinterpret_cast<uint32_t*>(smc + OQ + r * QPB + c * 2) = *(uint32_t*)&h2;
    }
    __syncthreads();

    uint32_t qf[8][4];
    {
        const uint32_t qA = sb + OQ + (16 * w + rowA) * QPB + colA * 2;
        #pragma unroll
        for (int k16 = 0; k16 < 8; k16++) ldm4(qf[k16], qA + k16 * 32);
    }

    float o[16][4];
    #pragma unroll
    for (int j = 0; j < 16; j++)
        #pragma unroll
        for (int e = 0; e < 4; e++) o[j][e] = 0.f;
    float rsum_lo = 0.f, rsum_hi = 0.f;

    const int row_lo = qrow0 + 16 * w + g;
    const int row_hi = row_lo + 8;

    for (int tt = 0; tt < ntiles; ++tt) {
        const int kb = tt * BK;
        const bool last = (tt == ntiles - 1);

        CP_WAIT(0);          // K(tt) landed
        __syncthreads();     // visible to all; prior PV reads of V done

        // issue V(tt) (single buffer)
        {
            const __half* vs = vsrc0 + kb;
            #pragma unroll
            for (int u = 0; u < 8; u++) cpa16(vdst + u * 16, vs + u * 8);
            CP_COMMIT();
        }
        // prefetch K(tt+1)
        if (!last) {
            const __half* ks = ksrc0 + (size_t)(kb + BK) * NKVH * HD;
            const uint32_t kd = (tt & 1) ? kdst0 : kdst1;
            #pragma unroll
            for (int u = 0; u < 8; u++) cpa16(kd + u * 16, ks + u * 8);
            CP_COMMIT();
        }

        const uint32_t kB = (tt & 1) ? k1B : k0B;

        // ---- S = Q K^T (fp32 acc, registers) ----
        float s[8][4];
        #pragma unroll
        for (int j = 0; j < 8; j++)
            #pragma unroll
            for (int e = 0; e < 4; e++) s[j][e] = 0.f;

        #pragma unroll
        for (int k16 = 0; k16 < 8; ++k16) {
            #pragma unroll
            for (int nb = 0; nb < 4; ++nb) {
                uint32_t b[4];
                ldm4(b, kB + nb * 16 * KPB + k16 * 32);
                mma16(s[2 * nb], qf[k16], b);
                mma16(s[2 * nb + 1], qf[k16], b + 2);
            }
        }

        // ---- softmax in registers -> pk ----
        uint32_t pk[8][2];
        #pragma unroll
        for (int j = 0; j < 8; j++) {
            float e0 = ex2(s[j][0]), e1 = ex2(s[j][1]);
            float e2 = ex2(s[j][2]), e3 = ex2(s[j][3]);
            if (last) {
                int kc = kb + 8 * j + 2 * t4;
                if (kc     > row_lo) e0 = 0.f;
                if (kc + 1 > row_lo) e1 = 0.f;
                if (kc     > row_hi) e2 = 0.f;
                if (kc + 1 > row_hi) e3 = 0.f;
            }
            __half2 hlo = __floats2half2_rn(e0, e1);
            __half2 hhi = __floats2half2_rn(e2, e3);
            float2 plo = __half22float2(hlo);
            float2 phi = __half22float2(hhi);
            rsum_lo += plo.x + plo.y;
            rsum_hi += phi.x + phi.y;
            pk[j][0] = *(uint32_t*)&hlo;
            pk[j][1] = *(uint32_t*)&hhi;
        }

        // V(tt) landed (K(tt+1) may still be in flight)
        if (!last) { CP_WAIT(1); } else { CP_WAIT(0); }
        __syncthreads();

        // ---- O += P V (fp32 acc) ----
        #pragma unroll
        for (int kk = 0; kk < 4; ++kk) {
            uint32_t pa[4] = {pk[2 * kk][0], pk[2 * kk][1],
                              pk[2 * kk + 1][0], pk[2 * kk + 1][1]};
            #pragma unroll
            for (int nb = 0; nb < 8; ++nb) {
                uint32_t b[4];
                ldm4(b, vB + nb * 16 * VPB + kk * 32);
                mma16(o[2 * nb], pa, b);
                mma16(o[2 * nb + 1], pa, b + 2);
            }
        }
    }

    // ---- row sums across the quad ----
    rsum_lo += __shfl_xor_sync(0xffffffffu, rsum_lo, 1);
    rsum_lo += __shfl_xor_sync(0xffffffffu, rsum_lo, 2);
    rsum_hi += __shfl_xor_sync(0xffffffffu, rsum_hi, 1);
    rsum_hi += __shfl_xor_sync(0xffffffffu, rsum_hi, 2);
    const float inv_lo = 1.f / rsum_lo;
    const float inv_hi = 1.f / rsum_hi;

    // ---- normalize + store ----
    const int r_lo = qb * BQ + 16 * w + g;
    float* out_lo = out + ((size_t)r_lo * NH + h) * HD;
    float* out_hi = out + ((size_t)(r_lo + 8) * NH + h) * HD;
    #pragma unroll
    for (int j = 0; j < 16; j++) {
        int c = 8 * j + 2 * t4;
        float2 vlo = {o[j][0] * inv_lo, o[j][1] * inv_lo};
        float2 vhi = {o[j][2] * inv_hi, o[j][3] * inv_hi};
        *reinterpret_cast<float2*>(out_lo + c) = vlo;
        *reinterpret_cast<float2*>(out_hi + c) = vhi;
    }
}

// ---------------------------------------------------------------------------
extern "C" void kernel_launch(void* const* d_in, const int* in_sizes, int n_in,
                              void* d_out, int out_size) {
    const float* q    = (const float*)d_in[0];
    const float* k    = (const float*)d_in[1];
    const float* v    = (const float*)d_in[2];
    const float* kc   = (const float*)d_in[3];
    const float* vc   = (const float*)d_in[4];
    const int*   slot = (const int*)d_in[5];
    float*       out  = (float*)d_out;

    copy_k_kernel<<<(TTOT * NKVH * 32 + 255) / 256, 256>>>((const float4*)kc);
    dim3 tg(TTOT / 32, HD / 32, NKVH);
    build_vt_kernel<<<tg, dim3(32, 8)>>>(vc);
    scatter_kernel<<<(NQ * NKVH * 32 + 255) / 256, 256>>>(
        (const float4*)k, (const float4*)v, slot);

    cudaFuncSetAttribute(attn_kernel,
                         cudaFuncAttributeMaxDynamicSharedMemorySize, SMB);
    attn_kernel<<<(NQ / BQ) * NH, 128, SMB>>>(q, out);
}

// round 12
// speedup vs baseline: 1.4161x; 1.4161x over previous
#include <cuda_runtime.h>
#include <cuda_fp16.h>
#include <cstdint>

#define NQ    2048
#define NH    32
#define NKVH  8
#define HD    128
#define CHUNK 2048
#define TTOT  4096
#define BQ    128
#define BK    64

#define QSCALE (0.08838834764831845f * 1.4426950408889634f)

#define QPB  272
#define KPB  272
#define VPB  144

// smem layout (bytes): 104 KB -> 2 CTAs/SM
#define OQ   0                  // 128 x 272
#define OK0  34816              // 64 x 272
#define OK1  52224
#define OV0  69632              // 128 x 144
#define OV1  88064
#define SMB  106496

__device__ __align__(16) __half g_K [(size_t)TTOT * NKVH * HD];   // [t][kvh][hd]
__device__ __align__(16) __half g_Vt[(size_t)NKVH * HD * TTOT];   // [kvh][hd][t]

// ---------------- helpers ----------------
__device__ __forceinline__ float ex2(float x) {
    float y; asm("ex2.approx.ftz.f32 %0, %1;" : "=f"(y) : "f"(x)); return y;
}
__device__ __forceinline__ void mma16(float* d, const uint32_t* a, const uint32_t* b) {
    asm volatile(
        "mma.sync.aligned.m16n8k16.row.col.f32.f16.f16.f32 "
        "{%0,%1,%2,%3}, {%4,%5,%6,%7}, {%8,%9}, {%0,%1,%2,%3};"
        : "+f"(d[0]), "+f"(d[1]), "+f"(d[2]), "+f"(d[3])
        : "r"(a[0]), "r"(a[1]), "r"(a[2]), "r"(a[3]), "r"(b[0]), "r"(b[1]));
}
__device__ __forceinline__ void ldm4(uint32_t* r, uint32_t addr) {
    asm volatile("ldmatrix.sync.aligned.m8n8.x4.shared.b16 {%0,%1,%2,%3}, [%4];"
        : "=r"(r[0]), "=r"(r[1]), "=r"(r[2]), "=r"(r[3]) : "r"(addr));
}
__device__ __forceinline__ uint32_t s2u(const void* p) {
    uint32_t a;
    asm("{ .reg .u64 t; cvta.to.shared.u64 t, %1; cvt.u32.u64 %0, t; }" : "=r"(a) : "l"(p));
    return a;
}
__device__ __forceinline__ void cpa16(uint32_t dst, const void* src) {
    asm volatile("cp.async.cg.shared.global [%0], [%1], 16;" :: "r"(dst), "l"(src) : "memory");
}
#define CP_COMMIT() asm volatile("cp.async.commit_group;" ::: "memory")
#define CP_WAIT(n)  asm volatile("cp.async.wait_group %0;" :: "n"(n) : "memory")

// ---------------------------------------------------------------------------
// Prep kernels (unchanged)
// ---------------------------------------------------------------------------
__global__ void copy_k_kernel(const float4* __restrict__ kc) {
    int idx = blockIdx.x * blockDim.x + threadIdx.x;
    if (idx >= TTOT * NKVH * (HD / 4)) return;
    float4 a = kc[idx];
    __half2 h0 = __floats2half2_rn(a.x, a.y);
    __half2 h1 = __floats2half2_rn(a.z, a.w);
    uint2 u = {*(uint32_t*)&h0, *(uint32_t*)&h1};
    reinterpret_cast<uint2*>(g_K)[idx] = u;
}

__global__ void build_vt_kernel(const float* __restrict__ vc) {
    __shared__ float sm[32][33];
    const int t0 = blockIdx.x * 32, hd0 = blockIdx.y * 32, kvh = blockIdx.z;
    const int tx = threadIdx.x, ty = threadIdx.y;
    #pragma unroll
    for (int i = 0; i < 4; i++) {
        int t = t0 + ty + 8 * i;
        sm[ty + 8 * i][tx] = vc[((size_t)t * NKVH + kvh) * HD + hd0 + tx];
    }
    __syncthreads();
    #pragma unroll
    for (int i = 0; i < 4; i++) {
        int hd = hd0 + ty + 8 * i;
        g_Vt[((size_t)kvh * HD + hd) * TTOT + t0 + tx] = __float2half_rn(sm[tx][ty + 8 * i]);
    }
}

__global__ void scatter_kernel(const float4* __restrict__ k,
                               const float4* __restrict__ v,
                               const int* __restrict__ slot) {
    int idx = blockIdx.x * blockDim.x + threadIdx.x;
    if (idx >= NQ * NKVH * (HD / 4)) return;
    int hd4 = idx & 31, kvh = (idx >> 5) & 7, row = idx >> 8;
    int s = slot[row];
    if ((unsigned)s >= (unsigned)TTOT) return;
    float4 a = k[idx];
    __half2 h0 = __floats2half2_rn(a.x, a.y);
    __half2 h1 = __floats2half2_rn(a.z, a.w);
    uint2 u = {*(uint32_t*)&h0, *(uint32_t*)&h1};
    reinterpret_cast<uint2*>(g_K)[(s * NKVH + kvh) * 32 + hd4] = u;
    float4 b = v[idx];
    __half* vt = g_Vt + ((size_t)kvh * HD + hd4 * 4) * TTOT + s;
    vt[0]        = __float2half_rn(b.x);
    vt[TTOT]     = __float2half_rn(b.y);
    vt[2 * TTOT] = __float2half_rn(b.z);
    vt[3 * TTOT] = __float2half_rn(b.w);
}

// ---------------------------------------------------------------------------
// Attention: FA2, fp32-acc, reg-P. 512 CTAs x 256 threads (8 warps, M-split
// 16 rows/warp, BQ=128). Q A-frags reloaded from smem per step (reg diet);
// __launch_bounds__(256,2) -> 2 independent CTAs/SM (16 warps/SM).
// ---------------------------------------------------------------------------
__global__ __launch_bounds__(256, 2)
void attn_kernel(const float* __restrict__ q, float* __restrict__ out) {
    extern __shared__ char smc[];
    const uint32_t sb = s2u(smc);

    const int tid = threadIdx.x;
    const int lane = tid & 31;
    const int w = tid >> 5;
    const int g = lane >> 2, t4 = lane & 3;

    const int bid = blockIdx.x;
    const int h = bid & 31;
    const int qb = (NQ / BQ) - 1 - (bid >> 5);
    const int kvh = h >> 2;

    const int ntiles = (CHUNK + (qb + 1) * BQ) / BK;
    const int qrow0 = CHUNK + qb * BQ;

    // ldmatrix lane offsets
    const int rowA = lane & 15;
    const int colA = (lane >> 4) * 8;
    const int rowB = (lane & 7) + (lane >> 4) * 8;
    const int colB = ((lane >> 3) & 1) * 8;

    const uint32_t qA  = sb + OQ + (16 * w + rowA) * QPB + colA * 2;
    const uint32_t k0B = sb + OK0 + rowB * KPB + colB * 2;
    const uint32_t k1B = sb + OK1 + rowB * KPB + colB * 2;
    const uint32_t v0B = sb + OV0 + rowB * VPB + colB * 2;
    const uint32_t v1B = sb + OV1 + rowB * VPB + colB * 2;

    // cp.async: K 64 rows x 256B (4 thr/row, 64B each); V 128 rows x 128B (2 thr/row)
    const int krow = tid >> 2, kch = (tid & 3) * 32;
    const __half* ksrc0 = g_K + ((size_t)krow * NKVH + kvh) * HD + kch;
    const uint32_t kdst0 = sb + OK0 + krow * KPB + kch * 2;
    const uint32_t kdst1 = sb + OK1 + krow * KPB + kch * 2;
    const int vrow = tid >> 1, vch = (tid & 1) * 32;
    const __half* vsrc0 = g_Vt + ((size_t)kvh * HD + vrow) * TTOT + vch;
    const uint32_t vdst0 = sb + OV0 + vrow * VPB + vch * 2;
    const uint32_t vdst1 = sb + OV1 + vrow * VPB + vch * 2;

    // ---- prologue: issue K(0)+V(0) ----
    #pragma unroll
    for (int u = 0; u < 4; u++) cpa16(kdst0 + u * 16, ksrc0 + u * 8);
    #pragma unroll
    for (int u = 0; u < 4; u++) cpa16(vdst0 + u * 16, vsrc0 + u * 8);
    CP_COMMIT();

    // ---- Q to smem (scaled fp16) ----
    for (int e = tid; e < BQ * (HD / 2); e += 256) {
        int r = e >> 6, c = (e & 63) * 2;
        const float* src = q + ((size_t)(qb * BQ + r) * NH + h) * HD + c;
        __half2 h2 = __floats2half2_rn(src[0] * QSCALE, src[1] * QSCALE);
        *reinterpret_cast<uint32_t*>(smc + OQ + r * QPB + c * 2) = *(uint32_t*)&h2;
    }

    float o[16][4];
    #pragma unroll
    for (int j = 0; j < 16; j++)
        #pragma unroll
        for (int e = 0; e < 4; e++) o[j][e] = 0.f;
    float rsum_lo = 0.f, rsum_hi = 0.f;

    const int row_lo = qrow0 + 16 * w + g;
    const int row_hi = row_lo + 8;

    __syncthreads();   // Q visible before first QK

    for (int tt = 0; tt < ntiles; ++tt) {
        const int kb = tt * BK;
        const bool last = (tt == ntiles - 1);

        CP_WAIT(0);          // K(tt), V(tt) landed
        __syncthreads();

        // issue K(tt+1)+V(tt+1) into the other buffers
        if (!last) {
            const __half* ks = ksrc0 + (size_t)(kb + BK) * NKVH * HD;
            const __half* vs = vsrc0 + kb + BK;
            const uint32_t kd = (tt & 1) ? kdst0 : kdst1;
            const uint32_t vd = (tt & 1) ? vdst0 : vdst1;
            #pragma unroll
            for (int u = 0; u < 4; u++) cpa16(kd + u * 16, ks + u * 8);
            #pragma unroll
            for (int u = 0; u < 4; u++) cpa16(vd + u * 16, vs + u * 8);
            CP_COMMIT();
        }

        const uint32_t kB = (tt & 1) ? k1B : k0B;
        const uint32_t vB = (tt & 1) ? v1B : v0B;

        // ---- S = Q K^T (fp32 acc; Q frag reloaded per step) ----
        float s[8][4];
        #pragma unroll
        for (int j = 0; j < 8; j++)
            #pragma unroll
            for (int e = 0; e < 4; e++) s[j][e] = 0.f;

        #pragma unroll
        for (int k16 = 0; k16 < 8; ++k16) {
            uint32_t a[4];
            ldm4(a, qA + k16 * 32);
            #pragma unroll
            for (int nb = 0; nb < 4; ++nb) {
                uint32_t b[4];
                ldm4(b, kB + nb * 16 * KPB + k16 * 32);
                mma16(s[2 * nb], a, b);
                mma16(s[2 * nb + 1], a, b + 2);
            }
        }

        // ---- softmax in registers -> pk ----
        uint32_t pk[8][2];
        #pragma unroll
        for (int j = 0; j < 8; j++) {
            float e0 = ex2(s[j][0]), e1 = ex2(s[j][1]);
            float e2 = ex2(s[j][2]), e3 = ex2(s[j][3]);
            if (tt >= ntiles - 2) {
                int kc = kb + 8 * j + 2 * t4;
                if (kc     > row_lo) e0 = 0.f;
                if (kc + 1 > row_lo) e1 = 0.f;
                if (kc     > row_hi) e2 = 0.f;
                if (kc + 1 > row_hi) e3 = 0.f;
            }
            __half2 hlo = __floats2half2_rn(e0, e1);
            __half2 hhi = __floats2half2_rn(e2, e3);
            float2 plo = __half22float2(hlo);
            float2 phi = __half22float2(hhi);
            rsum_lo += plo.x + plo.y;
            rsum_hi += phi.x + phi.y;
            pk[j][0] = *(uint32_t*)&hlo;
            pk[j][1] = *(uint32_t*)&hhi;
        }

        // ---- O += P V (fp32 acc, P from registers) ----
        #pragma unroll
        for (int kk = 0; kk < 4; ++kk) {
            uint32_t pa[4] = {pk[2 * kk][0], pk[2 * kk][1],
                              pk[2 * kk + 1][0], pk[2 * kk + 1][1]};
            #pragma unroll
            for (int nb = 0; nb < 8; ++nb) {
                uint32_t b[4];
                ldm4(b, vB + nb * 16 * VPB + kk * 32);
                mma16(o[2 * nb], pa, b);
                mma16(o[2 * nb + 1], pa, b + 2);
            }
        }
    }

    // ---- row sums across the quad ----
    rsum_lo += __shfl_xor_sync(0xffffffffu, rsum_lo, 1);
    rsum_lo += __shfl_xor_sync(0xffffffffu, rsum_lo, 2);
    rsum_hi += __shfl_xor_sync(0xffffffffu, rsum_hi, 1);
    rsum_hi += __shfl_xor_sync(0xffffffffu, rsum_hi, 2);
    const float inv_lo = 1.f / rsum_lo;
    const float inv_hi = 1.f / rsum_hi;

    // ---- normalize + store ----
    const int r_lo = qb * BQ + 16 * w + g;
    float* out_lo = out + ((size_t)r_lo * NH + h) * HD;
    float* out_hi = out + ((size_t)(r_lo + 8) * NH + h) * HD;
    #pragma unroll
    for (int j = 0; j < 16; j++) {
        int c = 8 * j + 2 * t4;
        float2 vlo = {o[j][0] * inv_lo, o[j][1] * inv_lo};
        float2 vhi = {o[j][2] * inv_hi, o[j][3] * inv_hi};
        *reinterpret_cast<float2*>(out_lo + c) = vlo;
        *reinterpret_cast<float2*>(out_hi + c) = vhi;
    }
}

// ---------------------------------------------------------------------------
extern "C" void kernel_launch(void* const* d_in, const int* in_sizes, int n_in,
                              void* d_out, int out_size) {
    const float* q    = (const float*)d_in[0];
    const float* k    = (const float*)d_in[1];
    const float* v    = (const float*)d_in[2];
    const float* kc   = (const float*)d_in[3];
    const float* vc   = (const float*)d_in[4];
    const int*   slot = (const int*)d_in[5];
    float*       out  = (float*)d_out;

    copy_k_kernel<<<(TTOT * NKVH * 32 + 255) / 256, 256>>>((const float4*)kc);
    dim3 tg(TTOT / 32, HD / 32, NKVH);
    build_vt_kernel<<<tg, dim3(32, 8)>>>(vc);
    scatter_kernel<<<(NQ * NKVH * 32 + 255) / 256, 256>>>(
        (const float4*)k, (const float4*)v, slot);

    cudaFuncSetAttribute(attn_kernel,
                         cudaFuncAttributeMaxDynamicSharedMemorySize, SMB);
    attn_kernel<<<(NQ / BQ) * NH, 256, SMB>>>(q, out);
}